// round 3
// baseline (speedup 1.0000x reference)
#include <cuda_runtime.h>
#include <cstdint>

// out[e,o] = xsum[e] * sum_r (1/cs[e,r]) * Wsum[r,o]
// E=100000, R=64, I=O=256. edge_index unused.

#define R_DIM 64
#define O_DIM 256
#define I_DIM 256
#define TE    32          // entities per block (main)

__device__ float g_Wpart[16][R_DIM * O_DIM];   // 1 MB per slice set
__device__ float g_Wsum[R_DIM * O_DIM];

// ---------------------------------------------------------------------------
// k1: partial Wsum over 16-row i-chunks. grid (64, 16) = 1024 blocks.
// ---------------------------------------------------------------------------
__global__ void wsum_part_kernel(const float* __restrict__ W) {
    int r = blockIdx.x, c = blockIdx.y, o = threadIdx.x;
    const float* base = W + (size_t)r * (I_DIM * O_DIM) + (size_t)c * 16 * O_DIM + o;
    float s0 = 0.f, s1 = 0.f, s2 = 0.f, s3 = 0.f;
#pragma unroll
    for (int i = 0; i < 16; i += 4) {
        s0 += base[(i + 0) * O_DIM];
        s1 += base[(i + 1) * O_DIM];
        s2 += base[(i + 2) * O_DIM];
        s3 += base[(i + 3) * O_DIM];
    }
    g_Wpart[c][r * O_DIM + o] = (s0 + s1) + (s2 + s3);
}

// ---------------------------------------------------------------------------
// k2: reduce 16 partials. 64 blocks x 256 threads; all data L2-resident.
// ---------------------------------------------------------------------------
__global__ void wsum_reduce_kernel() {
    int idx = blockIdx.x * 256 + threadIdx.x;
    float s = 0.f;
#pragma unroll
    for (int k = 0; k < 16; k++) s += g_Wpart[k][idx];
    g_Wsum[idx] = s;
}

// ---------------------------------------------------------------------------
// k3: fused main. 256 threads compute a TE(32) x 256 tile.
//   1) xsum: 8 threads/entity reduce the x row (coalesced float4 loads).
//   2) c2[e][r] = xsum[e]/cs[e,r], duplicated into both f32x2 lanes (smem).
//   3) register-tiled FFMA2 GEMM: thread (tc=tid&31, te=tid>>5) owns
//      4 entities x 4 col-pairs -> 16 packed accumulators (32 regs).
//      Inner loop per r: 2 LDS.128 (w) + 4 broadcast LDS.64 (c) + 16 FFMA2.
//   smem: w2 64KB + c2 16KB (dynamic), s_xsum 128B (static).
// ---------------------------------------------------------------------------
__global__ void __launch_bounds__(256, 2)
rgcn_main_kernel(const float* __restrict__ x, const float* __restrict__ cs,
                 float* __restrict__ out, int E) {
    extern __shared__ unsigned long long sm[];
    unsigned long long* w2 = sm;                       // 8192 ull (64 KB)
    unsigned long long* c2 = sm + R_DIM * (O_DIM / 2); // 2048 ull (16 KB)
    __shared__ float s_xsum[TE];

    const int tid = threadIdx.x;
    const int e0 = blockIdx.x * TE;

    // Stage Wsum as packed col-pairs (memory layout already pairs adjacent o).
    const unsigned long long* gw = (const unsigned long long*)g_Wsum;
#pragma unroll
    for (int k = 0; k < 32; k++)
        w2[tid + k * 256] = gw[tid + k * 256];

    // xsum: 8 threads per entity, each reads 8 float4 (coalesced per group).
    {
        int el = tid >> 3, l8 = tid & 7;
        int e = e0 + el;
        float s = 0.f;
        if (e < E) {
            const float4* p = (const float4*)(x + (size_t)e * I_DIM);
#pragma unroll
            for (int jj = 0; jj < 8; jj++) {
                float4 v = p[l8 * 8 + jj];
                s += (v.x + v.y) + (v.z + v.w);
            }
        }
        s += __shfl_xor_sync(0xffffffffu, s, 1);
        s += __shfl_xor_sync(0xffffffffu, s, 2);
        s += __shfl_xor_sync(0xffffffffu, s, 4);
        if (l8 == 0) s_xsum[el] = s;
    }
    __syncthreads();

    // c2 staging: coalesced over cs (consecutive tid -> consecutive r).
#pragma unroll
    for (int k = 0; k < 8; k++) {
        int idx = tid + k * 256;          // idx = e*64 + r
        int e = idx >> 6, r = idx & 63;
        float c = 0.f;
        if (e0 + e < E)
            c = s_xsum[e] / cs[(size_t)(e0 + e) * R_DIM + r];
        unsigned long long u = (unsigned long long)__float_as_uint(c);
        c2[idx] = u | (u << 32);
    }
    __syncthreads();

    const int tc = tid & 31;   // col pairs tc*4..tc*4+3  (cols 8tc..8tc+7)
    const int te = tid >> 5;   // entities te*4..te*4+3

    unsigned long long acc[4][4];
#pragma unroll
    for (int j = 0; j < 4; j++)
#pragma unroll
        for (int k = 0; k < 4; k++) acc[j][k] = 0ull;

#pragma unroll 8
    for (int r = 0; r < R_DIM; r++) {
        ulonglong2 wa = *(const ulonglong2*)&w2[r * (O_DIM / 2) + tc * 4];
        ulonglong2 wb = *(const ulonglong2*)&w2[r * (O_DIM / 2) + tc * 4 + 2];
#pragma unroll
        for (int j = 0; j < 4; j++) {
            unsigned long long cv = c2[(te * 4 + j) * R_DIM + r];  // warp broadcast
            asm("fma.rn.f32x2 %0, %1, %2, %0;" : "+l"(acc[j][0]) : "l"(wa.x), "l"(cv));
            asm("fma.rn.f32x2 %0, %1, %2, %0;" : "+l"(acc[j][1]) : "l"(wa.y), "l"(cv));
            asm("fma.rn.f32x2 %0, %1, %2, %0;" : "+l"(acc[j][2]) : "l"(wb.x), "l"(cv));
            asm("fma.rn.f32x2 %0, %1, %2, %0;" : "+l"(acc[j][3]) : "l"(wb.y), "l"(cv));
        }
    }

    // Store: 8 consecutive floats per entity at col 8*tc (two 16B stores).
#pragma unroll
    for (int j = 0; j < 4; j++) {
        int e = e0 + te * 4 + j;
        if (e < E) {
            ulonglong2 v0; v0.x = acc[j][0]; v0.y = acc[j][1];
            ulonglong2 v1; v1.x = acc[j][2]; v1.y = acc[j][3];
            ulonglong2* dst = (ulonglong2*)(out + (size_t)e * O_DIM + tc * 8);
            dst[0] = v0;
            dst[1] = v1;
        }
    }
}

// ---------------------------------------------------------------------------
// Launch. Inputs: x f32 (E,256), cs f32 (E,64), W f32 (64,256,256),
// edge_index i64 (unused). Output f32 (E,256).
// ---------------------------------------------------------------------------
extern "C" void kernel_launch(void* const* d_in, const int* in_sizes, int n_in,
                              void* d_out, int out_size) {
    const float* x  = (const float*)d_in[0];
    const float* cs = (const float*)d_in[1];
    const float* W  = (const float*)d_in[2];
    float* out = (float*)d_out;

    int E = in_sizes[1] / R_DIM;

    static bool configured = false;
    if (!configured) {
        cudaFuncSetAttribute(rgcn_main_kernel,
                             cudaFuncAttributeMaxDynamicSharedMemorySize,
                             80 * 1024);
        configured = true;
    }

    dim3 wgrid(R_DIM, 16);
    wsum_part_kernel<<<wgrid, O_DIM>>>(W);
    wsum_reduce_kernel<<<64, 256>>>();

    int mblocks = (E + TE - 1) / TE;
    rgcn_main_kernel<<<mblocks, 256, 80 * 1024>>>(x, cs, out, E);
}

// round 4
// speedup vs baseline: 1.6653x; 1.6653x over previous
#include <cuda_runtime.h>
#include <cstdint>

// out[e,o] = xsum[e] * sum_r (1/cs[e,r]) * Wsum[r,o]
// E=100000, R=64, I=O=256. edge_index unused.

#define R_DIM 64
#define O_DIM 256
#define I_DIM 256
#define TE    64           // entities per tile (main)
#define MAIN_BLOCKS 296    // persistent: 2 per SM on 148 SMs

__device__ float g_Wpart[16][R_DIM * O_DIM];
__device__ float g_Wsum[R_DIM * O_DIM];
__device__ float g_xsum[100352];

// ---------------------------------------------------------------------------
// prep: blocks [0,1024) compute Wsum partials (r = b>>4, i-chunk = b&15);
//       blocks >= 1024 compute xsum (one warp per entity, 8/block).
// ---------------------------------------------------------------------------
__global__ void prep_kernel(const float* __restrict__ W,
                            const float* __restrict__ x, int E) {
    if (blockIdx.x < 1024) {
        int r = blockIdx.x >> 4, c = blockIdx.x & 15, o = threadIdx.x;
        const float* base = W + (size_t)r * (I_DIM * O_DIM) + (size_t)c * 16 * O_DIM + o;
        float s0 = 0.f, s1 = 0.f, s2 = 0.f, s3 = 0.f;
#pragma unroll
        for (int i = 0; i < 16; i += 4) {
            s0 += base[(i + 0) * O_DIM];
            s1 += base[(i + 1) * O_DIM];
            s2 += base[(i + 2) * O_DIM];
            s3 += base[(i + 3) * O_DIM];
        }
        g_Wpart[c][r * O_DIM + o] = (s0 + s1) + (s2 + s3);
    } else {
        int e = (blockIdx.x - 1024) * 8 + (threadIdx.x >> 5);
        int lane = threadIdx.x & 31;
        if (e >= E) return;
        const float4* p = (const float4*)(x + (size_t)e * I_DIM);
        float4 a = p[lane];
        float4 b = p[lane + 32];
        float s = (a.x + a.y) + (a.z + a.w) + (b.x + b.y) + (b.z + b.w);
#pragma unroll
        for (int off = 16; off; off >>= 1)
            s += __shfl_xor_sync(0xffffffffu, s, off);
        if (lane == 0) g_xsum[e] = s;
    }
}

// ---------------------------------------------------------------------------
// reduce 16 Wsum partials (L2-resident). 64 blocks x 256.
// ---------------------------------------------------------------------------
__global__ void wsum_reduce_kernel() {
    int idx = blockIdx.x * 256 + threadIdx.x;
    float s = 0.f;
#pragma unroll
    for (int k = 0; k < 16; k++) s += g_Wpart[k][idx];
    g_Wsum[idx] = s;
}

// ---------------------------------------------------------------------------
// main: persistent. 296 blocks x 256 threads, smem 96KB (occ 2).
//  w2 [64][128] ull (64KB): Wsum packed col-pairs, staged ONCE per block.
//  c2 [TE][64]  ull (32KB): xsum[e]/cs[e,r] duplicated lo/hi, rebuilt per tile.
//  Thread (tc=tid&31, te=tid>>5): 8 entities x 4 col-pairs.
//    col chunks: ull {2tc,2tc+1} (cols 4tc..4tc+3) and {64+2tc,64+2tc+1}
//    (cols 128+4tc..): lane stride 16B -> conflict-free LDS.128.
//  Inner loop per 2 r: 4 LDS.128 (w) + 8 broadcast LDS.128 (c) + 64 FFMA2.
//  cs for tile t+1 prefetched into registers under tile-t compute.
// ---------------------------------------------------------------------------
__global__ void __launch_bounds__(256, 2)
rgcn_main_kernel(const float* __restrict__ cs, float* __restrict__ out,
                 int E, int n_tiles) {
    extern __shared__ unsigned long long sm[];
    unsigned long long* w2 = sm;                 // 8192 ull
    unsigned long long* c2 = sm + 8192;          // 4096 ull

    const int tid = threadIdx.x;
    const int tc = tid & 31;
    const int te = tid >> 5;

    // Stage Wsum once (col pairs already adjacent in memory).
    const unsigned long long* gw = (const unsigned long long*)g_Wsum;
#pragma unroll
    for (int k = 0; k < 32; k++)
        w2[tid + k * 256] = gw[tid + k * 256];
    // (sync happens inside the tile loop before first use)

    const float4* csv = (const float4*)cs;

    // Prefetch cs for first tile.
    int t = blockIdx.x;
    float4 pf[4];
    {
        size_t base4 = (size_t)t * (TE * 16);     // 16 float4 per entity row
#pragma unroll
        for (int k = 0; k < 4; k++) {
            int idx4 = tid + k * 256;
            int el = idx4 >> 4;
            pf[k] = (t * TE + el < E) ? csv[base4 + idx4]
                                      : make_float4(1.f, 1.f, 1.f, 1.f);
        }
    }

    for (; t < n_tiles; t += MAIN_BLOCKS) {
        const int e0 = t * TE;

        // Build c2 from prefetched cs.
#pragma unroll
        for (int k = 0; k < 4; k++) {
            int idx4 = tid + k * 256;
            int el = idx4 >> 4;              // entity within tile
            int r0 = (idx4 & 15) * 4;        // 4 consecutive r
            float xs = (e0 + el < E) ? g_xsum[e0 + el] : 0.f;
            float c0 = __fdividef(xs, pf[k].x);
            float c1 = __fdividef(xs, pf[k].y);
            float c2v = __fdividef(xs, pf[k].z);
            float c3 = __fdividef(xs, pf[k].w);
            unsigned long long u0 = (unsigned long long)__float_as_uint(c0);
            unsigned long long u1 = (unsigned long long)__float_as_uint(c1);
            unsigned long long u2 = (unsigned long long)__float_as_uint(c2v);
            unsigned long long u3 = (unsigned long long)__float_as_uint(c3);
            ulonglong2 v0; v0.x = u0 | (u0 << 32); v0.y = u1 | (u1 << 32);
            ulonglong2 v1; v1.x = u2 | (u2 << 32); v1.y = u3 | (u3 << 32);
            *(ulonglong2*)&c2[el * R_DIM + r0]     = v0;
            *(ulonglong2*)&c2[el * R_DIM + r0 + 2] = v1;
        }
        __syncthreads();

        // Prefetch cs for next tile while computing this one.
        int tn = t + MAIN_BLOCKS;
        if (tn < n_tiles) {
            size_t base4 = (size_t)tn * (TE * 16);
#pragma unroll
            for (int k = 0; k < 4; k++) {
                int idx4 = tid + k * 256;
                int el = idx4 >> 4;
                pf[k] = (tn * TE + el < E) ? csv[base4 + idx4]
                                           : make_float4(1.f, 1.f, 1.f, 1.f);
            }
        }

        unsigned long long acc[8][4];
#pragma unroll
        for (int j = 0; j < 8; j++)
#pragma unroll
            for (int q = 0; q < 4; q++) acc[j][q] = 0ull;

#pragma unroll 2
        for (int r = 0; r < R_DIM; r += 2) {
            // w: conflict-free LDS.128 (lane stride 16B)
            ulonglong2 wa0 = *(const ulonglong2*)&w2[(r)     * 128 + 2 * tc];
            ulonglong2 wa1 = *(const ulonglong2*)&w2[(r)     * 128 + 64 + 2 * tc];
            ulonglong2 wb0 = *(const ulonglong2*)&w2[(r + 1) * 128 + 2 * tc];
            ulonglong2 wb1 = *(const ulonglong2*)&w2[(r + 1) * 128 + 64 + 2 * tc];
#pragma unroll
            for (int j = 0; j < 8; j++) {
                // broadcast LDS.128: c[e][r], c[e][r+1]
                ulonglong2 cc = *(const ulonglong2*)&c2[(te * 8 + j) * R_DIM + r];
                asm("fma.rn.f32x2 %0, %1, %2, %0;" : "+l"(acc[j][0]) : "l"(wa0.x), "l"(cc.x));
                asm("fma.rn.f32x2 %0, %1, %2, %0;" : "+l"(acc[j][1]) : "l"(wa0.y), "l"(cc.x));
                asm("fma.rn.f32x2 %0, %1, %2, %0;" : "+l"(acc[j][2]) : "l"(wa1.x), "l"(cc.x));
                asm("fma.rn.f32x2 %0, %1, %2, %0;" : "+l"(acc[j][3]) : "l"(wa1.y), "l"(cc.x));
                asm("fma.rn.f32x2 %0, %1, %2, %0;" : "+l"(acc[j][0]) : "l"(wb0.x), "l"(cc.y));
                asm("fma.rn.f32x2 %0, %1, %2, %0;" : "+l"(acc[j][1]) : "l"(wb0.y), "l"(cc.y));
                asm("fma.rn.f32x2 %0, %1, %2, %0;" : "+l"(acc[j][2]) : "l"(wb1.x), "l"(cc.y));
                asm("fma.rn.f32x2 %0, %1, %2, %0;" : "+l"(acc[j][3]) : "l"(wb1.y), "l"(cc.y));
            }
        }

        // Store: cols [4tc,4tc+4) and [128+4tc, 128+4tc+4) per entity.
#pragma unroll
        for (int j = 0; j < 8; j++) {
            int e = e0 + te * 8 + j;
            if (e < E) {
                ulonglong2 v0; v0.x = acc[j][0]; v0.y = acc[j][1];
                ulonglong2 v1; v1.x = acc[j][2]; v1.y = acc[j][3];
                *(ulonglong2*)(out + (size_t)e * O_DIM + 4 * tc)       = v0;
                *(ulonglong2*)(out + (size_t)e * O_DIM + 128 + 4 * tc) = v1;
            }
        }
        __syncthreads();   // protect c2 before next tile's rebuild
    }
}

// ---------------------------------------------------------------------------
// Launch. Inputs: x f32 (E,256), cs f32 (E,64), W f32 (64,256,256),
// edge_index i64 (unused). Output f32 (E,256).
// ---------------------------------------------------------------------------
extern "C" void kernel_launch(void* const* d_in, const int* in_sizes, int n_in,
                              void* d_out, int out_size) {
    const float* x  = (const float*)d_in[0];
    const float* cs = (const float*)d_in[1];
    const float* W  = (const float*)d_in[2];
    float* out = (float*)d_out;

    int E = in_sizes[1] / R_DIM;

    static bool configured = false;
    if (!configured) {
        cudaFuncSetAttribute(rgcn_main_kernel,
                             cudaFuncAttributeMaxDynamicSharedMemorySize,
                             96 * 1024);
        configured = true;
    }

    int xblocks = (E + 7) / 8;
    prep_kernel<<<1024 + xblocks, 256>>>(W, x, E);
    wsum_reduce_kernel<<<64, 256>>>();

    int n_tiles = (E + TE - 1) / TE;
    rgcn_main_kernel<<<MAIN_BLOCKS, 256, 96 * 1024>>>(cs, out, E, n_tiles);
}